// round 8
// baseline (speedup 1.0000x reference)
#include <cuda_runtime.h>
#include <cuda_bf16.h>
#include <math.h>

#define BB 4
#define NN 512
#define SIGN64 0x8000000000000000ull
#define C21 4.76837158203125e-7f   // 2^-21

// ---------------------------------------------------------------------------
// XLA:CPU inline expf (Cephes, llvm_ir_runtime GenerateVF32Exp), aarch64 FMA.
// DO NOT TOUCH — bit-exactness verified (R4+ passes, rel_err 1e-8).
// ---------------------------------------------------------------------------
__device__ __forceinline__ float xla_expf(float xin)
{
    float x = fminf(xin,  88.3762626647950f);
    x       = fmaxf(x,   -88.3762626647949f);
    float fx = floorf(fmaf(x, 1.44269504088896341f, 0.5f));
    float t1 = __fmul_rn(fx, 0.693359375f);
    float t2 = __fmul_rn(fx, -2.12194440e-4f);
    float xr = __fsub_rn(x, t1);
    xr       = __fsub_rn(xr, t2);
    float zz = __fmul_rn(xr, xr);
    float y  = fmaf(1.9875691500E-4f, xr, 1.3981999507E-3f);
    y = fmaf(y, xr, 8.3334519073E-3f);
    y = fmaf(y, xr, 4.1665795894E-2f);
    y = fmaf(y, xr, 1.6666665459E-1f);
    y = fmaf(y, xr, 5.0000001201E-1f);
    y = fmaf(y, zz, xr);
    y = __fadd_rn(y, 1.0f);
    int n = (int)fx;
    float p2n = __int_as_float((n + 127) << 23);
    return fmaxf(__fmul_rn(y, p2n), xin);
}

// XLA:CPU inline logf (Cephes, GenerateVF32Log). DO NOT TOUCH.
__device__ __forceinline__ float xla_logf(float xin)
{
    float x = fmaxf(xin, 1.17549435e-38f);
    int ix   = __float_as_int(x);
    int emm0 = (int)((unsigned int)ix >> 23) - 0x7e;
    float e  = (float)emm0;
    x = __int_as_float((ix & ~0x7f800000) | 0x3f000000);
    bool m = x < 0.707106781186547524f;
    float tmp = m ? x : 0.0f;
    x = __fsub_rn(x, 1.0f);
    e = __fsub_rn(e, m ? 1.0f : 0.0f);
    x = __fadd_rn(x, tmp);
    float z = __fmul_rn(x, x);
    float y = fmaf(7.0376836292E-2f, x, -1.1514610310E-1f);
    y = fmaf(y, x,  1.1676998740E-1f);
    y = fmaf(y, x, -1.2420140846E-1f);
    y = fmaf(y, x,  1.4249322787E-1f);
    y = fmaf(y, x, -1.6668057665E-1f);
    y = fmaf(y, x,  2.0000714765E-1f);
    y = fmaf(y, x, -2.4999993993E-1f);
    y = fmaf(y, x,  3.3333331174E-1f);
    y = __fmul_rn(y, x);
    y = __fmul_rn(y, z);
    y = fmaf(e, -2.12194440e-4f, y);
    y = fmaf(z, -0.5f, y);
    x = __fadd_rn(x, y);
    x = fmaf(e, 0.693359375f, x);
    return x;
}

__device__ __forceinline__ float cost_class_f(float x)
{
    float e   = xla_expf(-x);
    float p   = __fdiv_rn(1.0f, __fadd_rn(1.0f, e));
    float omp = __fsub_rn(1.0f, p);
    float lo  = xla_logf(__fadd_rn(omp, 1e-8f));
    float lp  = xla_logf(__fadd_rn(p,   1e-8f));
    float pp  = __fmul_rn(p,   p);
    float oo  = __fmul_rn(omp, omp);
    float neg = __fmul_rn(__fmul_rn(0.75f, pp), -lo);
    float pos = __fmul_rn(__fmul_rn(0.25f, oo), -lp);
    return __fsub_rn(pos, neg);
}

__device__ __forceinline__ float cost_entry_f(float cls, float px, float py,
                                              float gx, float gy)
{
    float coord = __fadd_rn(fabsf(__fsub_rn(px, gx)), fabsf(__fsub_rn(py, gy)));
    return __fadd_rn(cls, coord);
}

__device__ __forceinline__ unsigned sort32(float x)
{
    int i = __float_as_int(x);
    return (unsigned)(i ^ ((i >> 31) | (int)0x80000000));
}
__device__ __forceinline__ float unsort32(unsigned key)
{
    int i = (key & 0x80000000u) ? (int)(key ^ 0x80000000u) : (int)~key;
    return __int_as_float(i);
}
__device__ __forceinline__ unsigned long long sort64(double x)
{
    long long b = __double_as_longlong(x);
    return (b >= 0) ? ((unsigned long long)b ^ SIGN64) : ~(unsigned long long)b;
}
__device__ __forceinline__ double unsort64(unsigned long long k)
{
    long long b = (long long)((k & SIGN64) ? (k ^ SIGN64) : ~k);
    return __longlong_as_double(b);
}

// ---------------------------------------------------------------------------
// Kernel 1: C matrix + pred_idx outputs. grid=(NN,BB), block=NN. (unchanged)
// ---------------------------------------------------------------------------
__global__ void cost_kernel(const float* __restrict__ logits,
                            const float2* __restrict__ pred_pts,
                            const float2* __restrict__ gt_pts,
                            float* __restrict__ pred_out,
                            float* __restrict__ Cf)
{
    const int i = blockIdx.x;
    const int b = blockIdx.y;
    const int j = threadIdx.x;

    __shared__ float s_cls, s_px, s_py;
    if (j == 0) {
        s_cls = cost_class_f(logits[b * NN + i]);
        float2 pp = pred_pts[b * NN + i];
        s_px = pp.x; s_py = pp.y;
        pred_out[b * NN + i] = (float)i;
    }
    __syncthreads();

    float2 gp = gt_pts[b * NN + j];
    Cf[((size_t)b * NN + i) * NN + j] = cost_entry_f(s_cls, s_px, s_py, gp.x, gp.y);
}

// ---------------------------------------------------------------------------
// Kernel 2: reference-buggy LSA, single warp per batch, 16 cols/lane.
// Within a walk, v[unused] and u of walk rows are constant -> delta is OFF the
// critical path. Fast path: packed (f32-upper-key | col) + one u32 REDUX gives
// j1 directly; conservative second-min test forces exact-f64 slow path on any
// possible ambiguity (incl. packing collisions & exact ties).
// ---------------------------------------------------------------------------
__global__ void __launch_bounds__(32, 1)
lsa_kernel(const float* __restrict__ logits,
           const float2* __restrict__ pred_pts,
           const float2* __restrict__ gt_pts,
           float* __restrict__ gt_out)
{
    const int b     = blockIdx.x;
    const int t     = threadIdx.x;       // 0..31
    const int cbase = t * 16;            // first owned col (0-based)
    const unsigned FULL = 0xffffffffu;

    __shared__ float  s_cls[NN], s_px[NN], s_py[NN], s_gx[NN], s_gy[NN];
    __shared__ float  s_uf[NN + 1];
    __shared__ double s_u64[NN + 1];
    __shared__ double s_v64[NN + 1];
    __shared__ int    s_p[NN + 1];

    for (int r = t; r < NN; r += 32) {
        s_cls[r] = cost_class_f(logits[b * NN + r]);
        float2 pp = pred_pts[b * NN + r]; s_px[r] = pp.x; s_py[r] = pp.y;
        float2 g  = gt_pts[b * NN + r];   s_gx[r] = g.x;  s_gy[r] = g.y;
        s_uf[r + 1] = 0.0f; s_u64[r + 1] = 0.0; s_v64[r + 1] = 0.0; s_p[r + 1] = 0;
    }
    __syncwarp();

    float gx[16], gy[16];
    #pragma unroll
    for (int k = 0; k < 16; k++) { gx[k] = s_gx[cbase + k]; gy[k] = s_gy[cbase + k]; }

    for (int i = 1; i <= NN; ++i) {
        __syncwarp();                    // prior walk-end writes visible

        float vf[16], base[16];
        float myVmax = 0.0f;
        #pragma unroll
        for (int k = 0; k < 16; k++) {
            vf[k] = (float)s_v64[cbase + k + 1];
            float av = fabsf(vf[k]);
            base[k] = C21 * (2.0f * av + 8.0f);
            myVmax  = fmaxf(myVmax, av);
        }
        // nonneg floats: uint compare == float compare
        float vmaxAll = __uint_as_float(
            __reduce_max_sync(FULL, __float_as_uint(myVmax)));
        float eVmax = C21 * (2.0f * vmaxAll + 8.0f);

        unsigned usedMask = 0;
        int   j0idx = -1;
        float cls0 = s_cls[i - 1], px0 = s_px[i - 1], py0 = s_py[i - 1];
        float ui0f = 0.0f;               // u[i] == 0 at row start
        double ui064 = 0.0;
        double uiacc = 0.0;              // lane0: running u[i]

        for (;;) {
            if (j0idx >= 0) {
                unsigned d = (unsigned)(j0idx - cbase);
                if (d < 16u) usedMask |= 1u << d;
            }

            const float eu = C21 * 3.0f * fabsf(ui0f);
            unsigned upT[16];
            #pragma unroll
            for (int k = 0; k < 16; k++) {
                // bit-exact reference cost (rn, no contraction)
                float d1 = __fsub_rn(px0, gx[k]);
                float d2 = __fsub_rn(py0, gy[k]);
                float s  = __fadd_rn(fabsf(d1), fabsf(d2));
                float cf = __fadd_rn(cls0, s);
                float a  = __fsub_rn(cf, ui0f);
                float c  = __fsub_rn(a, vf[k]);
                float up = c + (base[k] + eu);
                unsigned key = (sort32(up) & 0xFFFFFE00u) | (unsigned)(cbase + k);
                upT[k] = (usedMask & (1u << k)) ? 0xFFFFFFFFu : key;
            }
            // 16-way min tree
            unsigned m;
            {
                unsigned a0 = umin(upT[0],  upT[1]),  a1 = umin(upT[2],  upT[3]);
                unsigned a2 = umin(upT[4],  upT[5]),  a3 = umin(upT[6],  upT[7]);
                unsigned a4 = umin(upT[8],  upT[9]),  a5 = umin(upT[10], upT[11]);
                unsigned a6 = umin(upT[12], upT[13]), a7 = umin(upT[14], upT[15]);
                unsigned b0 = umin(a0, a1), b1 = umin(a2, a3);
                unsigned b2 = umin(a4, a5), b3 = umin(a6, a7);
                m = umin(umin(b0, b1), umin(b2, b3));
            }
            unsigned wMin = __reduce_min_sync(FULL, m);
            int j1idx = (int)(wMin & 511u);

            // -------- speculative prefetch (independent of delta) --------
            int  i0n = s_p[j1idx + 1];
            bool brk = (i0n == 0);
            float ui0f_n = 0.0f, cls0n = 0.0f, px0n = 0.0f, py0n = 0.0f;
            double ui064_n = 0.0;
            if (!brk) {
                ui0f_n = s_uf[i0n]; ui064_n = s_u64[i0n];
                cls0n = s_cls[i0n - 1]; px0n = s_px[i0n - 1]; py0n = s_py[i0n - 1];
            }

            // -------- uniqueness check (second-min vs radius) --------
            unsigned m2;
            {
                unsigned q[16];
                #pragma unroll
                for (int k = 0; k < 16; k++)
                    q[k] = (upT[k] == wMin) ? 0xFFFFFFFFu : upT[k];
                unsigned a0 = umin(q[0],  q[1]),  a1 = umin(q[2],  q[3]);
                unsigned a2 = umin(q[4],  q[5]),  a3 = umin(q[6],  q[7]);
                unsigned a4 = umin(q[8],  q[9]),  a5 = umin(q[10], q[11]);
                unsigned a6 = umin(q[12], q[13]), a7 = umin(q[14], q[15]);
                unsigned b0 = umin(a0, a1), b1 = umin(a2, a3);
                unsigned b2 = umin(a4, a5), b3 = umin(a6, a7);
                m2 = umin(umin(b0, b1), umin(b2, b3));
            }
            unsigned wMin2 = __reduce_min_sync(FULL, m2);
            float boundf = unsort32((wMin & 0xFFFFFE00u) + 512u); // >= winner upper
            float up2f   = unsort32(wMin2 & 0xFFFFFE00u);         // <= 2nd upper
            float eMax   = eVmax + eu;
            bool  slow   = !(up2f - 2.0f * eMax > boundf);        // uniform

            double delta;
            if (slow) {
                // -------- exact f64 argmin over all unused cols (rare) ----
                unsigned long long bk = ~0ull; int bc = 1024;
                #pragma unroll
                for (int k = 0; k < 16; k++) {
                    if (!(usedMask & (1u << k))) {
                        float d1 = __fsub_rn(px0, gx[k]);
                        float d2 = __fsub_rn(py0, gy[k]);
                        float s  = __fadd_rn(fabsf(d1), fabsf(d2));
                        float cf = __fadd_rn(cls0, s);
                        double cd = ((double)cf - ui064) - s_v64[cbase + k + 1];
                        unsigned long long kk = sort64(cd);
                        if (kk < bk) { bk = kk; bc = cbase + k; } // lowest col tie
                    }
                }
                unsigned hi  = (unsigned)(bk >> 32);
                unsigned mhi = __reduce_min_sync(FULL, hi);
                unsigned lo  = (hi == mhi) ? (unsigned)bk : 0xffffffffu;
                unsigned mlo = __reduce_min_sync(FULL, lo);
                unsigned long long mk = ((unsigned long long)mhi << 32) | mlo;
                unsigned ball = __ballot_sync(FULL, bk == mk);
                int src = __ffs(ball) - 1;
                j1idx = __shfl_sync(FULL, bc, src);
                delta = unsort64(mk);
                // redo prefetch with corrected j1
                i0n = s_p[j1idx + 1];
                brk = (i0n == 0);
                if (!brk) {
                    ui0f_n = s_uf[i0n]; ui064_n = s_u64[i0n];
                    cls0n = s_cls[i0n - 1]; px0n = s_px[i0n - 1]; py0n = s_py[i0n - 1];
                } else { ui0f_n = 0.0f; ui064_n = 0.0; }
            } else {
                // fast: winner lane computes exact f64 delta, broadcast
                int srcLane = j1idx >> 4;
                double cand64 = 0.0;
                if (t == srcLane) {
                    float gxw = s_gx[j1idx], gyw = s_gy[j1idx];
                    float d1 = __fsub_rn(px0, gxw);
                    float d2 = __fsub_rn(py0, gyw);
                    float s  = __fadd_rn(fabsf(d1), fabsf(d2));
                    float cfw = __fadd_rn(cls0, s);
                    cand64 = ((double)cfw - ui064) - s_v64[j1idx + 1];
                }
                delta = __shfl_sync(FULL, cand64, srcLane);
            }

            // -------- reference updates (sequential f64 rounding) --------
            unsigned um = usedMask;
            while (um) {
                int k = __ffs(um) - 1; um &= um - 1;
                int colx = cbase + k + 1;
                s_v64[colx] -= delta;
                int row = s_p[colx];
                s_u64[row] += delta;
            }
            if (t == 0) uiacc += delta;          // index 0: u[i]

            j0idx = j1idx;
            if (brk) break;
            ui0f = ui0f_n; ui064 = ui064_n;
            cls0 = cls0n; px0 = px0n; py0 = py0n;
        }

        // walk end: p[j_final] = i ; refresh f32 shadows of touched rows
        if (t == 0) {
            s_p[j0idx + 1] = i;
            s_u64[i] = uiacc;
            s_uf[i]  = (float)uiacc;
        }
        unsigned um = usedMask;
        while (um) {
            int k = __ffs(um) - 1; um &= um - 1;
            int row = s_p[cbase + k + 1];
            s_uf[row] = (float)s_u64[row];
        }
    }
    __syncwarp();

    #pragma unroll
    for (int k = 0; k < 16; k++) {
        int col = cbase + k + 1;
        gt_out[b * NN + (s_p[col] - 1)] = (float)(col - 1);
    }
}

// ---------------------------------------------------------------------------
// out = [pred_idx (B*N) | gt_idx (B*N) | C (B*N*N)], float32
// ---------------------------------------------------------------------------
extern "C" void kernel_launch(void* const* d_in, const int* in_sizes, int n_in,
                              void* d_out, int out_size)
{
    const float*  logits   = (const float*) d_in[0];
    const float2* pred_pts = (const float2*)d_in[1];
    const float2* gt_pts   = (const float2*)d_in[2];
    // d_in[3] = gt_mask (all true, unused)

    float* out  = (float*)d_out;
    float* pred = out;
    float* gt   = out + BB * NN;
    float* Cf   = out + 2 * BB * NN;

    dim3 cgrid(NN, BB);
    cost_kernel<<<cgrid, NN>>>(logits, pred_pts, gt_pts, pred, Cf);
    lsa_kernel<<<BB, 32>>>(logits, pred_pts, gt_pts, gt);
}

// round 9
// speedup vs baseline: 2.1413x; 2.1413x over previous
#include <cuda_runtime.h>
#include <cuda_bf16.h>
#include <math.h>

#define BB 4
#define NN 512
#define SIGN64 0x8000000000000000ull
#define C21 4.76837158203125e-7f   // 2^-21 = 8 * 2^-24 slack factor

// ---------------------------------------------------------------------------
// XLA:CPU inline expf (Cephes). DO NOT TOUCH — bit-exact (R4+ passes).
// ---------------------------------------------------------------------------
__device__ __forceinline__ float xla_expf(float xin)
{
    float x = fminf(xin,  88.3762626647950f);
    x       = fmaxf(x,   -88.3762626647949f);
    float fx = floorf(fmaf(x, 1.44269504088896341f, 0.5f));
    float t1 = __fmul_rn(fx, 0.693359375f);
    float t2 = __fmul_rn(fx, -2.12194440e-4f);
    float xr = __fsub_rn(x, t1);
    xr       = __fsub_rn(xr, t2);
    float zz = __fmul_rn(xr, xr);
    float y  = fmaf(1.9875691500E-4f, xr, 1.3981999507E-3f);
    y = fmaf(y, xr, 8.3334519073E-3f);
    y = fmaf(y, xr, 4.1665795894E-2f);
    y = fmaf(y, xr, 1.6666665459E-1f);
    y = fmaf(y, xr, 5.0000001201E-1f);
    y = fmaf(y, zz, xr);
    y = __fadd_rn(y, 1.0f);
    int n = (int)fx;
    float p2n = __int_as_float((n + 127) << 23);
    return fmaxf(__fmul_rn(y, p2n), xin);
}

// XLA:CPU inline logf (Cephes). DO NOT TOUCH.
__device__ __forceinline__ float xla_logf(float xin)
{
    float x = fmaxf(xin, 1.17549435e-38f);
    int ix   = __float_as_int(x);
    int emm0 = (int)((unsigned int)ix >> 23) - 0x7e;
    float e  = (float)emm0;
    x = __int_as_float((ix & ~0x7f800000) | 0x3f000000);
    bool m = x < 0.707106781186547524f;
    float tmp = m ? x : 0.0f;
    x = __fsub_rn(x, 1.0f);
    e = __fsub_rn(e, m ? 1.0f : 0.0f);
    x = __fadd_rn(x, tmp);
    float z = __fmul_rn(x, x);
    float y = fmaf(7.0376836292E-2f, x, -1.1514610310E-1f);
    y = fmaf(y, x,  1.1676998740E-1f);
    y = fmaf(y, x, -1.2420140846E-1f);
    y = fmaf(y, x,  1.4249322787E-1f);
    y = fmaf(y, x, -1.6668057665E-1f);
    y = fmaf(y, x,  2.0000714765E-1f);
    y = fmaf(y, x, -2.4999993993E-1f);
    y = fmaf(y, x,  3.3333331174E-1f);
    y = __fmul_rn(y, x);
    y = __fmul_rn(y, z);
    y = fmaf(e, -2.12194440e-4f, y);
    y = fmaf(z, -0.5f, y);
    x = __fadd_rn(x, y);
    x = fmaf(e, 0.693359375f, x);
    return x;
}

__device__ __forceinline__ float cost_class_f(float x)
{
    float e   = xla_expf(-x);
    float p   = __fdiv_rn(1.0f, __fadd_rn(1.0f, e));
    float omp = __fsub_rn(1.0f, p);
    float lo  = xla_logf(__fadd_rn(omp, 1e-8f));
    float lp  = xla_logf(__fadd_rn(p,   1e-8f));
    float pp  = __fmul_rn(p,   p);
    float oo  = __fmul_rn(omp, omp);
    float neg = __fmul_rn(__fmul_rn(0.75f, pp), -lo);
    float pos = __fmul_rn(__fmul_rn(0.25f, oo), -lp);
    return __fsub_rn(pos, neg);
}

__device__ __forceinline__ float cost_entry_f(float cls, float px, float py,
                                              float gx, float gy)
{
    float coord = __fadd_rn(fabsf(__fsub_rn(px, gx)), fabsf(__fsub_rn(py, gy)));
    return __fadd_rn(cls, coord);
}

__device__ __forceinline__ unsigned sort32(float x)
{
    int i = __float_as_int(x);
    return (unsigned)(i ^ ((i >> 31) | (int)0x80000000));
}
__device__ __forceinline__ float unsort32(unsigned key)
{
    int i = (key & 0x80000000u) ? (int)(key ^ 0x80000000u) : (int)~key;
    return __int_as_float(i);
}
__device__ __forceinline__ unsigned long long sort64(double x)
{
    long long b = __double_as_longlong(x);
    return (b >= 0) ? ((unsigned long long)b ^ SIGN64) : ~(unsigned long long)b;
}
__device__ __forceinline__ double unsort64(unsigned long long k)
{
    long long b = (long long)((k & SIGN64) ? (k ^ SIGN64) : ~k);
    return __longlong_as_double(b);
}

// ---------------------------------------------------------------------------
// Kernel 1: C matrix + pred_idx outputs. (unchanged)
// ---------------------------------------------------------------------------
__global__ void cost_kernel(const float* __restrict__ logits,
                            const float2* __restrict__ pred_pts,
                            const float2* __restrict__ gt_pts,
                            float* __restrict__ pred_out,
                            float* __restrict__ Cf)
{
    const int i = blockIdx.x;
    const int b = blockIdx.y;
    const int j = threadIdx.x;

    __shared__ float s_cls, s_px, s_py;
    if (j == 0) {
        s_cls = cost_class_f(logits[b * NN + i]);
        float2 pp = pred_pts[b * NN + i];
        s_px = pp.x; s_py = pp.y;
        pred_out[b * NN + i] = (float)i;
    }
    __syncthreads();

    float2 gp = gt_pts[b * NN + j];
    Cf[((size_t)b * NN + i) * NN + j] = cost_entry_f(s_cls, s_px, s_py, gp.x, gp.y);
}

// ---------------------------------------------------------------------------
// Kernel 2: reference-buggy LSA. 128 threads/batch, 4 cols/lane (0-based).
// Fast path: packed (trunc-sortable-f32-upper | col) keys, per-warp (m1,m2)
// REDUX partials, ONE barrier/step. Window test vs conservative radii forces
// exact-f64 slow path (rare) -> bit-identical argmin+delta to reference.
// Deltas propagate with lag 1 (per-location sequential f64 order preserved).
// Shared state (p, u64-by-col, rowdata, shadows) mutates only at walk ends.
// ---------------------------------------------------------------------------
__global__ void __launch_bounds__(128, 1)
lsa_kernel(const float* __restrict__ logits,
           const float2* __restrict__ pred_pts,
           const float2* __restrict__ gt_pts,
           float* __restrict__ gt_out)
{
    const int b     = blockIdx.x;
    const int t     = threadIdx.x;
    const int w     = t >> 5;
    const int cbase = 4 * t;                     // first owned col, 0-based
    const unsigned FULL = 0xffffffffu;

    __shared__ float  s_cls[NN], s_px[NN], s_py[NN];
    __shared__ float4 s_rowd[NN];                // by col: {cls,px,py,uf} of p[col]
    __shared__ double s_ucol[NN];                // by col: u64 of p[col]
    __shared__ int    s_p[NN];                   // by col: matched row (1..), 0=free
    __shared__ unsigned long long s_part[4];     // (m2<<32)|m1 per warp
    __shared__ unsigned long long s_q64[4];      // slow-path exact partials
    __shared__ int    s_qc[4];
    __shared__ float  s_vmaxp[4];
    __shared__ double s_delta[2];                // parity slots

    for (int r = t; r < NN; r += 128) {
        s_cls[r] = cost_class_f(logits[b * NN + r]);
        float2 pp = pred_pts[b * NN + r]; s_px[r] = pp.x; s_py[r] = pp.y;
        s_p[r] = 0; s_ucol[r] = 0.0;
        s_rowd[r] = make_float4(0.f, 0.f, 0.f, 0.f);
    }
    float gx[4], gy[4];
    #pragma unroll
    for (int k = 0; k < 4; k++) {
        float2 g = gt_pts[b * NN + cbase + k];
        gx[k] = g.x; gy[k] = g.y;
    }
    double v64[4] = {0.0, 0.0, 0.0, 0.0};
    double uc[4]  = {0.0, 0.0, 0.0, 0.0};
    float  vf[4]  = {0.f, 0.f, 0.f, 0.f};
    float  vmaxAll = 0.0f;
    __syncthreads();

    for (int i = 1; i <= NN; ++i) {
        float baseR[4];
        #pragma unroll
        for (int k = 0; k < 4; k++)
            baseR[k] = C21 * (2.0f * fabsf(vf[k]) + 16.0f);
        const float eVbase = C21 * (2.0f * vmaxAll + 16.0f);

        unsigned applyMask = 0, pwBit = 0;
        int s = 1, j1 = -1;
        // row-start: current row = i, u[i]=0
        float  cls0 = s_cls[i - 1], px0 = s_px[i - 1], py0 = s_py[i - 1];
        float  ui0f = 0.0f;
        double ui064 = 0.0;
        double uiacc = 0.0;                      // t0: running u[i]

        for (;;) {
            const unsigned excl = applyMask | pwBit;
            const float euStep = C21 * 3.0f * fabsf(ui0f);
            const float eMax   = eVbase + euStep;

            // ---- f32 candidates with conservative upper bound, packed keys
            float cfv[4];
            unsigned key[4];
            #pragma unroll
            for (int k = 0; k < 4; k++) {
                float d1 = __fsub_rn(px0, gx[k]);
                float d2 = __fsub_rn(py0, gy[k]);
                float sa = __fadd_rn(fabsf(d1), fabsf(d2));
                cfv[k]   = __fadd_rn(cls0, sa);            // exact ref C entry
                float uv = __fadd_rn(ui0f, vf[k]);
                float c  = __fsub_rn(cfv[k], uv);          // approx cand
                float up = c + (baseR[k] + euStep);        // upper bound
                unsigned kk = (sort32(up) & 0xFFFFFE00u) | (unsigned)(cbase + k);
                key[k] = ((excl >> k) & 1u) ? 0xFFFFFFFFu : kk;
            }
            unsigned m1l = umin(umin(key[0], key[1]), umin(key[2], key[3]));
            unsigned m1w = __reduce_min_sync(FULL, m1l);
            unsigned q0 = (key[0] == m1w) ? 0xFFFFFFFFu : key[0];
            unsigned q1 = (key[1] == m1w) ? 0xFFFFFFFFu : key[1];
            unsigned q2 = (key[2] == m1w) ? 0xFFFFFFFFu : key[2];
            unsigned q3 = (key[3] == m1w) ? 0xFFFFFFFFu : key[3];
            unsigned m2l = umin(umin(q0, q1), umin(q2, q3));
            unsigned m2w = __reduce_min_sync(FULL, m2l);
            if ((t & 31) == 0)
                s_part[w] = ((unsigned long long)m2w << 32) | m1w;
            __syncthreads();                               // the ONLY fast barrier

            // ---- global stage-2 from 4 (m1,m2) partials
            unsigned long long P0 = s_part[0], P1 = s_part[1],
                               P2 = s_part[2], P3 = s_part[3];
            unsigned wMin1 = umin(umin((unsigned)P0, (unsigned)P1),
                                  umin((unsigned)P2, (unsigned)P3));
            j1 = (int)(wMin1 & 511u);

            // ---- issue prefetch immediately (overlaps slow check)
            int    pval = s_p[j1];
            float4 rd   = s_rowd[j1];
            double un64 = s_ucol[j1];

            unsigned e0 = ((unsigned)P0 == wMin1) ? (unsigned)(P0 >> 32) : (unsigned)P0;
            unsigned e1 = ((unsigned)P1 == wMin1) ? (unsigned)(P1 >> 32) : (unsigned)P1;
            unsigned e2 = ((unsigned)P2 == wMin1) ? (unsigned)(P2 >> 32) : (unsigned)P2;
            unsigned e3 = ((unsigned)P3 == wMin1) ? (unsigned)(P3 >> 32) : (unsigned)P3;
            unsigned second = umin(umin(e0, e1), umin(e2, e3));

            bool safe;
            if (second >= 0xFF000000u) safe = true;        // no finite competitor
            else {
                float bup = unsort32((wMin1 & 0xFFFFFE00u) + 0x200u);
                float slb = unsort32(second & 0xFFFFFE00u);
                safe = (slb - 2.0f * eMax > bup);
            }

            double delta;
            bool   haveDelta = false;
            if (!safe) {
                // ---- exact f64 argmin (rare; uniform branch)
                unsigned long long bk = ~0ull; int bc = 0;
                #pragma unroll
                for (int k = 0; k < 4; k++) {
                    if (!((excl >> k) & 1u)) {
                        double cd = ((double)cfv[k] - ui064) - v64[k];
                        unsigned long long kk = sort64(cd);
                        if (kk < bk) { bk = kk; bc = cbase + k; }
                    }
                }
                unsigned hi  = (unsigned)(bk >> 32);
                unsigned mhi = __reduce_min_sync(FULL, hi);
                unsigned lo  = (hi == mhi) ? (unsigned)bk : 0xffffffffu;
                unsigned mlo = __reduce_min_sync(FULL, lo);
                unsigned long long mk = ((unsigned long long)mhi << 32) | mlo;
                unsigned ball = __ballot_sync(FULL, bk == mk);
                int src = __ffs(ball) - 1;
                int wc  = __shfl_sync(FULL, bc, src);
                if ((t & 31) == 0) { s_q64[w] = mk; s_qc[w] = wc; }
                __syncthreads();
                unsigned long long gb = s_q64[0]; int gj = s_qc[0];
                #pragma unroll
                for (int w2 = 1; w2 < 4; w2++) {
                    unsigned long long kk = s_q64[w2];
                    if (kk < gb) { gb = kk; gj = s_qc[w2]; }
                }
                j1 = gj;
                delta = unsort64(gb);
                haveDelta = true;
                pval = s_p[j1];                 // redo prefetch
                rd   = s_rowd[j1];
                un64 = s_ucol[j1];
            }

            const bool brk = (pval == 0);

            // ---- phase 4: apply lagged delta d_{s-1} (winners of 1..s-2)
            if (s >= 2) {
                double d = s_delta[(s - 1) & 1];
                #pragma unroll
                for (int k = 0; k < 4; k++)
                    if ((applyMask >> k) & 1u) { v64[k] -= d; uc[k] += d; }
                if (t == 0) uiacc += d;
            }
            // ---- phase 5: advance masks; capture u64 of newly-won own col
            applyMask |= pwBit;
            {
                unsigned dd = (unsigned)(j1 - cbase);
                pwBit = (dd < 4u) ? (1u << dd) : 0u;
                if (dd < 4u) uc[dd] = un64;     // walk-start u of row p[j1]
            }
            // ---- phase 6: publish delta_s
            if (haveDelta) {
                if (t == 0) s_delta[s & 1] = delta;
            } else {
                unsigned dd = (unsigned)(j1 - cbase);
                if (dd < 4u) {
                    double cd = ((double)cfv[dd] - ui064) - v64[dd]; // exact ref
                    s_delta[s & 1] = cd;
                }
            }
            // ---- commit next-row state
            cls0 = rd.x; px0 = rd.y; py0 = rd.z; ui0f = rd.w;
            ui064 = un64;

            if (brk) break;
            s++;
        }

        // ---- walk end ----
        __syncthreads();                         // d_S + all step writes visible
        {
            double dS = s_delta[s & 1];
            #pragma unroll
            for (int k = 0; k < 4; k++)
                if ((applyMask >> k) & 1u) { v64[k] -= dS; uc[k] += dS; }
            if (t == 0) uiacc += dS;
        }
        // flush used cols' state; t0 installs new assignment
        #pragma unroll
        for (int k = 0; k < 4; k++) {
            if ((applyMask >> k) & 1u) {
                vf[k] = (float)v64[k];
                s_ucol[cbase + k]   = uc[k];
                s_rowd[cbase + k].w = (float)uc[k];
            }
        }
        if (t == 0) {
            s_p[j1]    = i;
            s_ucol[j1] = uiacc;
            s_rowd[j1] = make_float4(s_cls[i - 1], s_px[i - 1], s_py[i - 1],
                                     (float)uiacc);
        }
        // vmax for next row's radii
        float vm = fmaxf(fmaxf(fabsf(vf[0]), fabsf(vf[1])),
                         fmaxf(fabsf(vf[2]), fabsf(vf[3])));
        unsigned wvm = __reduce_max_sync(FULL, __float_as_uint(vm));
        if ((t & 31) == 0) s_vmaxp[w] = __uint_as_float(wvm);
        __syncthreads();                         // row-top barrier
        vmaxAll = fmaxf(fmaxf(s_vmaxp[0], s_vmaxp[1]),
                        fmaxf(s_vmaxp[2], s_vmaxp[3]));
    }
    __syncthreads();

    #pragma unroll
    for (int k = 0; k < 4; k++) {
        int col = cbase + k;
        gt_out[b * NN + (s_p[col] - 1)] = (float)col;
    }
}

// ---------------------------------------------------------------------------
// out = [pred_idx (B*N) | gt_idx (B*N) | C (B*N*N)], float32
// ---------------------------------------------------------------------------
extern "C" void kernel_launch(void* const* d_in, const int* in_sizes, int n_in,
                              void* d_out, int out_size)
{
    const float*  logits   = (const float*) d_in[0];
    const float2* pred_pts = (const float2*)d_in[1];
    const float2* gt_pts   = (const float2*)d_in[2];
    // d_in[3] = gt_mask (all true, unused)

    float* out  = (float*)d_out;
    float* pred = out;
    float* gt   = out + BB * NN;
    float* Cf   = out + 2 * BB * NN;

    dim3 cgrid(NN, BB);
    cost_kernel<<<cgrid, NN>>>(logits, pred_pts, gt_pts, pred, Cf);
    lsa_kernel<<<BB, 128>>>(logits, pred_pts, gt_pts, gt);
}